// round 16
// baseline (speedup 1.0000x reference)
#include <cuda_runtime.h>
#include <cuda_bf16.h>
#include <cstdint>

#define MAXN 50000
#define MAXE 800000
#define CH 96          // padded feature channels (88 real: 4 x + 84 edge_attr)
#define OC 128
#define OUTC 64
#define EPSV 1e-5f
#define SCAN_CH 2048   // elements per scan CTA

// ---------------- device scratch (static globals: no allocs allowed) -------
__device__ int   g_is64;
__device__ int   g_row[MAXE];
__device__ int   g_col[MAXE];
__device__ int   g_cnt[MAXN];
__device__ int   g_off[MAXN + 1];
__device__ int   g_cur[MAXN];
__device__ int   g_perm[MAXE];
__device__ int   g_srow[MAXE];             // row id in perm order (sorted)
__device__ int   g_blk[64];
__device__ float g_S[(size_t)MAXN * CH];   // per-node summed features
__device__ float g_M[CH * CH];             // second-moment matrix sum f f^T
__device__ float g_sv[CH];                 // global feature sum s
__device__ float g_mean[OC];
__device__ float g_scale[OC];              // gamma * rsqrt(var+eps)

__device__ __forceinline__ uint32_t smem_u32(const void* p) {
    uint32_t a;
    asm("{ .reg .u64 t; cvta.to.shared.u64 t, %1; cvt.u32.u64 %0, t; }" : "=r"(a) : "l"(p));
    return a;
}
__device__ __forceinline__ void fma2(unsigned long long& d,
                                     unsigned long long a, unsigned long long b) {
    asm("fma.rn.f32x2 %0, %1, %2, %0;" : "+l"(d) : "l"(a), "l"(b));
}
__device__ __forceinline__ unsigned long long packdup(float v) {
    unsigned long long r;
    asm("mov.b64 %0, {%1, %1};" : "=l"(r) : "f"(v));
    return r;
}
__device__ __forceinline__ unsigned long long pack2(float lo, float hi) {
    unsigned long long r;
    asm("mov.b64 %0, {%1, %2};" : "=l"(r) : "f"(lo), "f"(hi));
    return r;
}

// ---------------- host-side stream/event set (created once, pre-main) ------
struct HxStreams {
    cudaStream_t s1;
    cudaEvent_t evFork, evJoin;
    HxStreams() {
        cudaStreamCreateWithFlags(&s1, cudaStreamNonBlocking);
        cudaEventCreateWithFlags(&evFork, cudaEventDisableTiming);
        cudaEventCreateWithFlags(&evJoin, cudaEventDisableTiming);
    }
};
static HxStreams g_hx;

// ---------------- detect dtype + zero g_cnt (critical-path-minimal) --------
__global__ void k_init_small(const void* ei, int N) {
    int i = blockIdx.x * blockDim.x + threadIdx.x;
    int T = gridDim.x * blockDim.x;
    for (int j = i; j < N; j += T) g_cnt[j] = 0;
    if (blockIdx.x == 0 && threadIdx.x < 32) {
        const long long* p = (const long long*)ei;
        int bad = 0;
        for (int k = threadIdx.x; k < 64; k += 32) {
            long long v = p[k];
            if (v < 0 || v >= MAXN) bad = 1;
        }
        unsigned m = __ballot_sync(0xffffffffu, bad);
        if (threadIdx.x == 0) g_is64 = (m == 0) ? 1 : 0;
    }
}

// ---------------- zero big scratch (parallel stream; no dependencies) ------
__global__ void k_zero_big(int N) {
    int i = blockIdx.x * blockDim.x + threadIdx.x;
    int T = gridDim.x * blockDim.x;
    for (int j = i; j < CH * CH; j += T) g_M[j] = 0.f;
    size_t tot = (size_t)N * CH;
    for (size_t j = i; j < tot; j += T) g_S[j] = 0.f;
    if (i < CH) g_sv[i] = 0.f;
}

// ---------------- convert + histogram fused ---------------------------------
__global__ void k_convhist(const void* ei, int E) {
    int is64 = g_is64;
    int i = blockIdx.x * blockDim.x + threadIdx.x;
    int T = gridDim.x * blockDim.x;
    if (is64) {
        const long long* p = (const long long*)ei;
        for (int e = i; e < E; e += T) {
            int r = (int)p[e];
            g_row[e] = r; g_col[e] = (int)p[E + e];
            atomicAdd(&g_cnt[r], 1);
        }
    } else {
        const int* p = (const int*)ei;
        for (int e = i; e < E; e += T) {
            int r = p[e];
            g_row[e] = r; g_col[e] = p[E + e];
            atomicAdd(&g_cnt[r], 1);
        }
    }
}

// ---------------- multi-CTA exclusive scan ----------------------------------
__global__ void k_scanA(int N) {
    __shared__ int sc[1024];
    int b = blockIdx.x, t = threadIdx.x;
    int i0 = b * SCAN_CH + t * 2;
    int c0 = (i0 < N) ? g_cnt[i0] : 0;
    int c1 = (i0 + 1 < N) ? g_cnt[i0 + 1] : 0;
    int s = c0 + c1;
    sc[t] = s;
    __syncthreads();
#pragma unroll
    for (int d = 1; d < 1024; d <<= 1) {
        int v = (t >= d) ? sc[t - d] : 0;
        __syncthreads();
        sc[t] += v;
        __syncthreads();
    }
    int excl = sc[t] - s;
    if (i0 < N) g_off[i0] = excl;
    if (i0 + 1 < N) g_off[i0 + 1] = excl + c0;
    if (t == 1023) g_blk[b] = sc[1023];
}

// scanC with the 25-entry block-sum scan done locally (scanB folded in)
__global__ void k_scanC(int N, int nb, int E) {
    __shared__ int pref[32];
    int t = threadIdx.x;
    if (t < 32) {
        int v = (t < nb) ? g_blk[t] : 0;
        int incl = v;
#pragma unroll
        for (int d = 1; d < 32; d <<= 1) {
            int u = __shfl_up_sync(0xffffffffu, incl, d);
            if (t >= d) incl += u;
        }
        pref[t] = incl - v;   // exclusive
    }
    __syncthreads();
    int i = blockIdx.x * blockDim.x + t;
    if (i < N) {
        int v = g_off[i] + pref[i >> 11];
        g_off[i] = v;
        g_cur[i] = v;
    }
    if (i == 0) g_off[N] = E;
}

__global__ void k_perm(int E) {
    int i = blockIdx.x * blockDim.x + threadIdx.x;
    int T = gridDim.x * blockDim.x;
    for (int e = i; e < E; e += T) {
        int r = g_row[e];
        int p = atomicAdd(&g_cur[r], 1);
        g_perm[p] = e;
        g_srow[p] = r;
    }
}

// ---------------- FUSED: M = sum f f^T (HMMA) + per-node S (seg-reduce) ----
// KB=256: one __syncthreads per 256 edges; prev chunk's 16 K-steps split into
// two mma-halves slotted under the first two gather-load shadows.
#define KB 256
#define ROWB 528
#define TILE_B (CH * ROWB)   // 50688

__device__ __forceinline__ void ldm_x4(uint32_t* r, uint32_t a) {
    asm volatile("ldmatrix.sync.aligned.m8n8.x4.shared.b16 {%0,%1,%2,%3}, [%4];"
                 : "=r"(r[0]), "=r"(r[1]), "=r"(r[2]), "=r"(r[3]) : "r"(a));
}
__device__ __forceinline__ void ldm_x2(uint32_t* r, uint32_t a) {
    asm volatile("ldmatrix.sync.aligned.m8n8.x2.shared.b16 {%0,%1}, [%2];"
                 : "=r"(r[0]), "=r"(r[1]) : "r"(a));
}
__device__ __forceinline__ void mma_bf16(float* c, const uint32_t* a, const uint32_t* b) {
    asm volatile("mma.sync.aligned.m16n8k16.row.col.f32.bf16.bf16.f32 "
                 "{%0,%1,%2,%3}, {%4,%5,%6,%7}, {%8,%9}, {%0,%1,%2,%3};"
                 : "+f"(c[0]), "+f"(c[1]), "+f"(c[2]), "+f"(c[3])
                 : "r"(a[0]), "r"(a[1]), "r"(a[2]), "r"(a[3]), "r"(b[0]), "r"(b[1]));
}

__device__ __forceinline__ void fused_load8(const float* __restrict__ x,
                                            const float* __restrict__ ea, int E,
                                            long long base0, int lane,
                                            float* v0, float* v1, float* v2, int* rw) {
#pragma unroll
    for (int u = 0; u < 8; u++) {
        long long idx = base0 + u;
        int ok = idx < E;
        long long ide = ok ? idx : (long long)(E - 1);
        int e = g_perm[ide];
        rw[u] = g_srow[ide];
        const float* fe = ea + (size_t)e * 84;
        float p, q, r;
        if (lane < 4) p = x[g_col[e] * 4 + lane];
        else          p = __ldcs(fe + lane - 4);
        q = __ldcs(fe + 28 + lane);
        r = (lane < 24) ? __ldcs(fe + 60 + lane) : 0.f;
        float m = ok ? 1.f : 0.f;
        v0[u] = m * p; v1[u] = m * q; v2[u] = m * r;
    }
}

// half of the 16 K-steps of a KB=256 tile
__device__ __forceinline__ void mma_half(const char* tp, int Rm, int Rn, int lane,
                                         int ks0, float acc[3][3][4]) {
    uint32_t tb = smem_u32(tp);
#pragma unroll
    for (int kk = 0; kk < 8; kk++) {
        int ks = ks0 + kk;
        uint32_t af[3][4], bf[3][2];
#pragma unroll
        for (int i = 0; i < 3; i++) {
            uint32_t addr = tb + (uint32_t)((Rm + i * 16 + (lane & 15)) * ROWB
                                            + ks * 32 + (lane >> 4) * 16);
            ldm_x4(af[i], addr);
        }
#pragma unroll
        for (int j = 0; j < 3; j++) {
            uint32_t addr = tb + (uint32_t)((Rn + j * 8 + (lane & 7)) * ROWB
                                            + ks * 32 + ((lane >> 3) & 1) * 16);
            ldm_x2(bf[j], addr);
        }
#pragma unroll
        for (int i = 0; i < 3; i++)
#pragma unroll
            for (int j = 0; j < 3; j++) mma_bf16(acc[i][j], af[i], bf[j]);
    }
}

__global__ void __launch_bounds__(256, 2)
k_fused(const float* __restrict__ x, const float* __restrict__ ea, int E) {
    extern __shared__ __align__(16) char dsm[];   // 2 * TILE_B
    int tid = threadIdx.x;
    int lane = tid & 31, w = tid >> 5;
    int warp_m = w >> 2, warp_n = w & 3;   // 2 x 4
    int Rm = warp_m * 48;                  // 3 x 16 rows
    int Rn = warp_n * 24;                  // 3 x 8 cols

    float acc[3][3][4];
#pragma unroll
    for (int i = 0; i < 3; i++)
#pragma unroll
        for (int j = 0; j < 3; j++)
#pragma unroll
            for (int q = 0; q < 4; q++) acc[i][j][q] = 0.f;

    float s0 = 0.f, s1 = 0.f, s2 = 0.f;
    float aS0 = 0.f, aS1 = 0.f, aS2 = 0.f;
    int curRow = -1;

    int nchunk = (E + KB - 1) / KB;
    int wbuf = 0, have = 0;
    for (int c = blockIdx.x; c < nchunk; c += gridDim.x) {
        long long base = (long long)c * KB;
        char* tp = dsm + wbuf * TILE_B;
        const char* pv = dsm + (wbuf ^ 1) * TILE_B;
        float v0[8], v1[8], v2[8];
        int rw[8];

#pragma unroll
        for (int g = 0; g < 4; g++) {
            // issue this group's gather LDGs (scoreboard pending)
            fused_load8(x, ea, E, base + w * 32 + g * 8, lane, v0, v1, v2, rw);
            // overlap: half of previous chunk's MMA under the load shadow
            if (have && g < 2) mma_half(pv, Rm, Rn, lane, g * 8, acc);
            // consume: pack/store + seg-reduce
            int ee0 = w * 32 + g * 8;
#pragma unroll
            for (int u = 0; u < 8; u += 2) {
                s0 += v0[u] + v0[u + 1];
                s1 += v1[u] + v1[u + 1];
                s2 += v2[u] + v2[u + 1];
                __nv_bfloat162 b0 = __floats2bfloat162_rn(v0[u], v0[u + 1]);
                __nv_bfloat162 b1 = __floats2bfloat162_rn(v1[u], v1[u + 1]);
                __nv_bfloat162 b2 = __floats2bfloat162_rn(v2[u], v2[u + 1]);
                int eo = (ee0 + u) * 2;
                *(__nv_bfloat162*)(tp + lane * ROWB + eo) = b0;
                *(__nv_bfloat162*)(tp + (32 + lane) * ROWB + eo) = b1;
                *(__nv_bfloat162*)(tp + (64 + lane) * ROWB + eo) = b2;
            }
#pragma unroll
            for (int u = 0; u < 8; u++) {
                if (rw[u] != curRow) {
                    if (curRow >= 0) {
                        float* dst = g_S + (size_t)curRow * CH;
                        atomicAdd(&dst[lane], aS0);
                        atomicAdd(&dst[32 + lane], aS1);
                        if (lane < 24) atomicAdd(&dst[64 + lane], aS2);
                    }
                    curRow = rw[u];
                    aS0 = 0.f; aS1 = 0.f; aS2 = 0.f;
                }
                aS0 += v0[u]; aS1 += v1[u]; aS2 += v2[u];
            }
        }
        __syncthreads();   // stores of wbuf visible; prior mma on wbuf^1 complete
        have = 1;
        wbuf ^= 1;
    }
    // epilogue: MMA for the last stored chunk
    if (have) {
        const char* pv = dsm + (wbuf ^ 1) * TILE_B;
        mma_half(pv, Rm, Rn, lane, 0, acc);
        mma_half(pv, Rm, Rn, lane, 8, acc);
    }

    if (curRow >= 0) {
        float* dst = g_S + (size_t)curRow * CH;
        atomicAdd(&dst[lane], aS0);
        atomicAdd(&dst[32 + lane], aS1);
        if (lane < 24) atomicAdd(&dst[64 + lane], aS2);
    }
#pragma unroll
    for (int i = 0; i < 3; i++)
#pragma unroll
        for (int j = 0; j < 3; j++) {
            int row = Rm + i * 16 + (lane >> 2);
            int col = Rn + j * 8 + (lane & 3) * 2;
            atomicAdd(&g_M[row * CH + col], acc[i][j][0]);
            atomicAdd(&g_M[row * CH + col + 1], acc[i][j][1]);
            atomicAdd(&g_M[(row + 8) * CH + col], acc[i][j][2]);
            atomicAdd(&g_M[(row + 8) * CH + col + 1], acc[i][j][3]);
        }
    atomicAdd(&g_sv[lane], s0);
    atomicAdd(&g_sv[32 + lane], s1);
    if (lane < 24) atomicAdd(&g_sv[64 + lane], s2);
}

// ---------------- BN stats --------------------------------------------------
__global__ void k_bn(const float* __restrict__ W1, const float* __restrict__ b1,
                     const float* __restrict__ gamma, float fE) {
    int c = blockIdx.x;
    int t = threadIdx.x;  // 96 threads
    __shared__ float w[CH];
    __shared__ float rq[CH];
    __shared__ float rs[CH];
    w[t] = (t < 88) ? W1[t * OC + c] : 0.f;
    __syncthreads();
    float q = 0.f;
    if (t < 88) {
        const float* Mr = g_M + t * CH;
        for (int k = 0; k < 88; k++) q += Mr[k] * w[k];
        q *= w[t];
    }
    rq[t] = q;
    rs[t] = (t < 88) ? g_sv[t] * w[t] : 0.f;
    __syncthreads();
    if (t == 0) {
        float Q = 0.f, SW = 0.f;
        for (int i = 0; i < 88; i++) { Q += rq[i]; SW += rs[i]; }
        float b = b1[c];
        float mean = SW / fE + b;
        float ex2 = (Q + 2.f * b * SW) / fE + b * b;
        float var = ex2 - mean * mean;
        g_mean[c] = mean;
        g_scale[c] = gamma[c] * rsqrtf(var + EPSV);
    }
}

// ---------------- node output: f32x2 packed math, 4 nodes per warp ----------
__global__ void k_out(const float* __restrict__ x, const float* __restrict__ W1,
                      const float* __restrict__ b1, const float* __restrict__ beta,
                      const float* __restrict__ W2, const float* __restrict__ b2,
                      float* __restrict__ out, int N) {
    extern __shared__ float2 smp[];
    float2* W1pA = smp;                // 2816
    float2* W1pB = smp + 88 * 32;      // 2816
    float2* W2p  = smp + 2 * 88 * 32;  // 4224
    int tid = threadIdx.x;
    for (int i = tid; i < 88 * 32; i += blockDim.x) {
        int cc = i >> 5, l = i & 31;
        W1pA[i] = make_float2(W1[cc * OC + l], W1[cc * OC + 32 + l]);
        W1pB[i] = make_float2(W1[cc * OC + 64 + l], W1[cc * OC + 96 + l]);
    }
    for (int i = tid; i < 132 * 32; i += blockDim.x) {
        int cc = i >> 5, l = i & 31;
        W2p[i] = make_float2(W2[cc * OUTC + l], W2[cc * OUTC + 32 + l]);
    }
    __syncthreads();
    int lane = tid & 31;
    int warp = (blockIdx.x * blockDim.x + tid) >> 5;
    int nw = (gridDim.x * blockDim.x) >> 5;
    float mn0 = g_mean[lane], mn1 = g_mean[32 + lane], mn2 = g_mean[64 + lane], mn3 = g_mean[96 + lane];
    float sc0 = g_scale[lane], sc1 = g_scale[32 + lane], sc2 = g_scale[64 + lane], sc3 = g_scale[96 + lane];
    float bt0 = beta[lane], bt1 = beta[32 + lane], bt2 = beta[64 + lane], bt3 = beta[96 + lane];
    float bo0 = b1[lane], bo1 = b1[32 + lane], bo2 = b1[64 + lane], bo3 = b1[96 + lane];
    float bb0 = b2[lane], bb1 = b2[32 + lane];
    unsigned long long bbP = pack2(bb0, bb1);

    for (int n0 = warp * 4; n0 < N; n0 += nw * 4) {
        float sr0[4], sr1[4], sr2[4], rcp[4], tv[4];
#pragma unroll
        for (int m = 0; m < 4; m++) {
            int n = n0 + m;
            if (n < N) {
                const float* so = g_S + (size_t)n * CH;
                sr0[m] = so[lane]; sr1[m] = so[32 + lane]; sr2[m] = so[64 + lane];
                int cnt = g_off[n + 1] - g_off[n];
                tv[m] = (cnt > 0) ? 1.f : 0.f;
                rcp[m] = (cnt > 0) ? 1.f / (float)cnt : 0.f;
            } else { sr0[m] = sr1[m] = sr2[m] = 0.f; tv[m] = 0.f; rcp[m] = 0.f; }
        }
        unsigned long long aA[4], aB[4];
#pragma unroll
        for (int m = 0; m < 4; m++) { aA[m] = 0ull; aB[m] = 0ull; }
#pragma unroll
        for (int cc = 0; cc < 32; cc++) {
            unsigned long long wA = *(const unsigned long long*)&W1pA[cc * 32 + lane];
            unsigned long long wB = *(const unsigned long long*)&W1pB[cc * 32 + lane];
#pragma unroll
            for (int m = 0; m < 4; m++) {
                unsigned long long vv = packdup(__shfl_sync(0xffffffffu, sr0[m], cc));
                fma2(aA[m], vv, wA); fma2(aB[m], vv, wB);
            }
        }
#pragma unroll
        for (int cc = 0; cc < 32; cc++) {
            unsigned long long wA = *(const unsigned long long*)&W1pA[(32 + cc) * 32 + lane];
            unsigned long long wB = *(const unsigned long long*)&W1pB[(32 + cc) * 32 + lane];
#pragma unroll
            for (int m = 0; m < 4; m++) {
                unsigned long long vv = packdup(__shfl_sync(0xffffffffu, sr1[m], cc));
                fma2(aA[m], vv, wA); fma2(aB[m], vv, wB);
            }
        }
#pragma unroll
        for (int cc = 0; cc < 24; cc++) {
            unsigned long long wA = *(const unsigned long long*)&W1pA[(64 + cc) * 32 + lane];
            unsigned long long wB = *(const unsigned long long*)&W1pB[(64 + cc) * 32 + lane];
#pragma unroll
            for (int m = 0; m < 4; m++) {
                unsigned long long vv = packdup(__shfl_sync(0xffffffffu, sr2[m], cc));
                fma2(aA[m], vv, wA); fma2(aB[m], vv, wB);
            }
        }
        float ag0[4], ag1[4], ag2[4], ag3[4];
#pragma unroll
        for (int m = 0; m < 4; m++) {
            float2 vA = *(float2*)&aA[m];
            float2 vB = *(float2*)&aB[m];
            ag0[m] = ((vA.x * rcp[m] + bo0 - mn0) * sc0 + bt0) * tv[m];
            ag1[m] = ((vA.y * rcp[m] + bo1 - mn1) * sc1 + bt1) * tv[m];
            ag2[m] = ((vB.x * rcp[m] + bo2 - mn2) * sc2 + bt2) * tv[m];
            ag3[m] = ((vB.y * rcp[m] + bo3 - mn3) * sc3 + bt3) * tv[m];
        }
        unsigned long long oP[4];
#pragma unroll
        for (int m = 0; m < 4; m++) oP[m] = bbP;
#pragma unroll
        for (int k = 0; k < 4; k++) {
            unsigned long long wp = *(const unsigned long long*)&W2p[k * 32 + lane];
#pragma unroll
            for (int m = 0; m < 4; m++) {
                int n = n0 + m;
                float xv = (n < N) ? x[(size_t)n * 4 + k] : 0.f;
                fma2(oP[m], packdup(xv), wp);
            }
        }
#pragma unroll
        for (int cc = 0; cc < 32; cc++) {
            unsigned long long wp = *(const unsigned long long*)&W2p[(4 + cc) * 32 + lane];
#pragma unroll
            for (int m = 0; m < 4; m++)
                fma2(oP[m], packdup(__shfl_sync(0xffffffffu, ag0[m], cc)), wp);
        }
#pragma unroll
        for (int cc = 0; cc < 32; cc++) {
            unsigned long long wp = *(const unsigned long long*)&W2p[(36 + cc) * 32 + lane];
#pragma unroll
            for (int m = 0; m < 4; m++)
                fma2(oP[m], packdup(__shfl_sync(0xffffffffu, ag1[m], cc)), wp);
        }
#pragma unroll
        for (int cc = 0; cc < 32; cc++) {
            unsigned long long wp = *(const unsigned long long*)&W2p[(68 + cc) * 32 + lane];
#pragma unroll
            for (int m = 0; m < 4; m++)
                fma2(oP[m], packdup(__shfl_sync(0xffffffffu, ag2[m], cc)), wp);
        }
#pragma unroll
        for (int cc = 0; cc < 32; cc++) {
            unsigned long long wp = *(const unsigned long long*)&W2p[(100 + cc) * 32 + lane];
#pragma unroll
            for (int m = 0; m < 4; m++)
                fma2(oP[m], packdup(__shfl_sync(0xffffffffu, ag3[m], cc)), wp);
        }
#pragma unroll
        for (int m = 0; m < 4; m++) {
            int n = n0 + m;
            if (n < N) {
                float2 o = *(float2*)&oP[m];
                out[(size_t)n * 64 + lane] = fmaxf(o.x, 0.f);
                out[(size_t)n * 64 + 32 + lane] = fmaxf(o.y, 0.f);
            }
        }
    }
}

// ---------------- launcher --------------------------------------------------
extern "C" void kernel_launch(void* const* d_in, const int* in_sizes, int n_in,
                              void* d_out, int out_size) {
    const float* x     = (const float*)d_in[0];
    const void*  ei    = d_in[1];
    const float* ea    = (const float*)d_in[2];
    const float* W1    = (const float*)d_in[3];
    const float* b1    = (const float*)d_in[4];
    const float* gamma = (const float*)d_in[5];
    const float* beta  = (const float*)d_in[6];
    const float* W2    = (const float*)d_in[7];
    const float* b2    = (const float*)d_in[8];
    float* out = (float*)d_out;
    int N = in_sizes[0] / 4;
    int E = in_sizes[2] / 84;
    int nb = (N + SCAN_CH - 1) / SCAN_CH;

    // fork: root the side stream in the capture stream, then zero big scratch
    cudaEventRecord(g_hx.evFork, 0);
    cudaStreamWaitEvent(g_hx.s1, g_hx.evFork, 0);
    k_zero_big<<<512, 256, 0, g_hx.s1>>>(N);
    cudaEventRecord(g_hx.evJoin, g_hx.s1);

    // main chain
    k_init_small<<<128, 256>>>(ei, N);
    k_convhist<<<512, 256>>>(ei, E);
    k_scanA<<<nb, 1024>>>(N);
    k_scanC<<<(N + 255) / 256, 256>>>(N, nb, E);
    k_perm<<<1024, 256>>>(E);

    // join: fused needs g_M/g_sv/g_S zeroed
    cudaStreamWaitEvent(0, g_hx.evJoin, 0);
    const int msmem = 2 * TILE_B;   // 101376 B
    cudaFuncSetAttribute(k_fused, cudaFuncAttributeMaxDynamicSharedMemorySize, msmem);
    k_fused<<<296, 256, msmem>>>(x, ea, E);

    k_bn<<<128, 96>>>(W1, b1, gamma, (float)E);
    const int osmem = (2 * 88 * 32 + 132 * 32) * 8;  // 78848 B
    cudaFuncSetAttribute(k_out, cudaFuncAttributeMaxDynamicSharedMemorySize, osmem);
    k_out<<<296, 256, osmem>>>(x, W1, b1, beta, W2, b2, out, N);
}

// round 17
// speedup vs baseline: 1.0841x; 1.0841x over previous
#include <cuda_runtime.h>
#include <cuda_bf16.h>
#include <cstdint>

#define MAXN 50000
#define MAXE 800000
#define CH 96          // padded feature channels (88 real: 4 x + 84 edge_attr)
#define OC 128
#define OUTC 64
#define EPSV 1e-5f
#define SCAN_CH 2048   // elements per scan CTA

// ---------------- device scratch (static globals: no allocs allowed) -------
__device__ int   g_is64;
__device__ int   g_row[MAXE];
__device__ int   g_col[MAXE];
__device__ int   g_cnt[MAXN];
__device__ int   g_off[MAXN + 1];
__device__ int   g_cur[MAXN];
__device__ int   g_perm[MAXE];
__device__ int   g_srow[MAXE];             // row id in perm order (sorted)
__device__ int   g_blk[64];
__device__ float g_S[(size_t)MAXN * CH];   // per-node summed features
__device__ float g_M[CH * CH];             // second-moment matrix sum f f^T
__device__ float g_sv[CH];                 // global feature sum s
__device__ float g_mean[OC];
__device__ float g_scale[OC];              // gamma * rsqrt(var+eps)

__device__ __forceinline__ uint32_t smem_u32(const void* p) {
    uint32_t a;
    asm("{ .reg .u64 t; cvta.to.shared.u64 t, %1; cvt.u32.u64 %0, t; }" : "=r"(a) : "l"(p));
    return a;
}
__device__ __forceinline__ void fma2(unsigned long long& d,
                                     unsigned long long a, unsigned long long b) {
    asm("fma.rn.f32x2 %0, %1, %2, %0;" : "+l"(d) : "l"(a), "l"(b));
}
__device__ __forceinline__ unsigned long long packdup(float v) {
    unsigned long long r;
    asm("mov.b64 %0, {%1, %1};" : "=l"(r) : "f"(v));
    return r;
}
__device__ __forceinline__ unsigned long long pack2(float lo, float hi) {
    unsigned long long r;
    asm("mov.b64 %0, {%1, %2};" : "=l"(r) : "f"(lo), "f"(hi));
    return r;
}

// ---------------- dtype detection: int64 vs int32 edge_index ----------------
__global__ void k_detect(const void* ei) {
    const long long* p = (const long long*)ei;
    int bad = 0;
    for (int i = threadIdx.x; i < 64; i += 32) {
        long long v = p[i];
        if (v < 0 || v >= MAXN) bad = 1;
    }
    unsigned m = __ballot_sync(0xffffffffu, bad);
    if (threadIdx.x == 0) g_is64 = (m == 0) ? 1 : 0;
}

// ---------------- zero scratch (g_cnt, g_M, g_sv, g_S) ----------------------
__global__ void k_zero(int N) {
    int i = blockIdx.x * blockDim.x + threadIdx.x;
    int T = gridDim.x * blockDim.x;
    for (int j = i; j < N; j += T) g_cnt[j] = 0;
    for (int j = i; j < CH * CH; j += T) g_M[j] = 0.f;
    size_t tot = (size_t)N * CH;
    for (size_t j = i; j < tot; j += T) g_S[j] = 0.f;
    if (i < CH) g_sv[i] = 0.f;
}

// ---------------- convert + histogram fused ---------------------------------
__global__ void k_convhist(const void* ei, int E) {
    int is64 = g_is64;
    int i = blockIdx.x * blockDim.x + threadIdx.x;
    int T = gridDim.x * blockDim.x;
    if (is64) {
        const long long* p = (const long long*)ei;
        for (int e = i; e < E; e += T) {
            int r = (int)p[e];
            g_row[e] = r; g_col[e] = (int)p[E + e];
            atomicAdd(&g_cnt[r], 1);
        }
    } else {
        const int* p = (const int*)ei;
        for (int e = i; e < E; e += T) {
            int r = p[e];
            g_row[e] = r; g_col[e] = p[E + e];
            atomicAdd(&g_cnt[r], 1);
        }
    }
}

// ---------------- multi-CTA exclusive scan ----------------------------------
__global__ void k_scanA(int N) {
    __shared__ int sc[1024];
    int b = blockIdx.x, t = threadIdx.x;
    int i0 = b * SCAN_CH + t * 2;
    int c0 = (i0 < N) ? g_cnt[i0] : 0;
    int c1 = (i0 + 1 < N) ? g_cnt[i0 + 1] : 0;
    int s = c0 + c1;
    sc[t] = s;
    __syncthreads();
#pragma unroll
    for (int d = 1; d < 1024; d <<= 1) {
        int v = (t >= d) ? sc[t - d] : 0;
        __syncthreads();
        sc[t] += v;
        __syncthreads();
    }
    int excl = sc[t] - s;
    if (i0 < N) g_off[i0] = excl;
    if (i0 + 1 < N) g_off[i0 + 1] = excl + c0;
    if (t == 1023) g_blk[b] = sc[1023];
}

// scanC with the 25-entry block-sum scan done locally (scanB folded in)
__global__ void k_scanC(int N, int nb, int E) {
    __shared__ int pref[32];
    int t = threadIdx.x;
    if (t < 32) {
        int v = (t < nb) ? g_blk[t] : 0;
        int incl = v;
#pragma unroll
        for (int d = 1; d < 32; d <<= 1) {
            int u = __shfl_up_sync(0xffffffffu, incl, d);
            if (t >= d) incl += u;
        }
        pref[t] = incl - v;   // exclusive
    }
    __syncthreads();
    int i = blockIdx.x * blockDim.x + t;
    if (i < N) {
        int v = g_off[i] + pref[i >> 11];
        g_off[i] = v;
        g_cur[i] = v;
    }
    if (i == 0) g_off[N] = E;
}

__global__ void k_perm(int E) {
    int i = blockIdx.x * blockDim.x + threadIdx.x;
    int T = gridDim.x * blockDim.x;
    for (int e = i; e < E; e += T) {
        int r = g_row[e];
        int p = atomicAdd(&g_cur[r], 1);
        g_perm[p] = e;
        g_srow[p] = r;
    }
}

// ---------------- FUSED: M = sum f f^T (HMMA) + per-node S (seg-reduce) ----
// Software-pipelined: chunk c's gather LDGs issue BEFORE chunk c-1's MMA phase,
// so the HMMA work executes under the DRAM-latency shadow. KB=128 (proven opt).
#define KB 128
#define ROWB 272
#define TILE_B (CH * ROWB)   // 26112

__device__ __forceinline__ void ldm_x4(uint32_t* r, uint32_t a) {
    asm volatile("ldmatrix.sync.aligned.m8n8.x4.shared.b16 {%0,%1,%2,%3}, [%4];"
                 : "=r"(r[0]), "=r"(r[1]), "=r"(r[2]), "=r"(r[3]) : "r"(a));
}
__device__ __forceinline__ void ldm_x2(uint32_t* r, uint32_t a) {
    asm volatile("ldmatrix.sync.aligned.m8n8.x2.shared.b16 {%0,%1}, [%2];"
                 : "=r"(r[0]), "=r"(r[1]) : "r"(a));
}
__device__ __forceinline__ void mma_bf16(float* c, const uint32_t* a, const uint32_t* b) {
    asm volatile("mma.sync.aligned.m16n8k16.row.col.f32.bf16.bf16.f32 "
                 "{%0,%1,%2,%3}, {%4,%5,%6,%7}, {%8,%9}, {%0,%1,%2,%3};"
                 : "+f"(c[0]), "+f"(c[1]), "+f"(c[2]), "+f"(c[3])
                 : "r"(a[0]), "r"(a[1]), "r"(a[2]), "r"(a[3]), "r"(b[0]), "r"(b[1]));
}

__device__ __forceinline__ void fused_load8(const float* __restrict__ x,
                                            const float* __restrict__ ea, int E,
                                            long long base0, int lane,
                                            float* v0, float* v1, float* v2, int* rw) {
#pragma unroll
    for (int u = 0; u < 8; u++) {
        long long idx = base0 + u;
        int ok = idx < E;
        long long ide = ok ? idx : (long long)(E - 1);
        int e = g_perm[ide];
        rw[u] = g_srow[ide];
        const float* fe = ea + (size_t)e * 84;
        float p, q, r;
        if (lane < 4) p = x[g_col[e] * 4 + lane];
        else          p = __ldcs(fe + lane - 4);
        q = __ldcs(fe + 28 + lane);
        r = (lane < 24) ? __ldcs(fe + 60 + lane) : 0.f;
        float m = ok ? 1.f : 0.f;
        v0[u] = m * p; v1[u] = m * q; v2[u] = m * r;
    }
}

__device__ __forceinline__ void mma_phase(const char* tp, int Rm, int Rn, int lane,
                                          float acc[3][3][4]) {
    uint32_t tb = smem_u32(tp);
#pragma unroll
    for (int ks = 0; ks < KB / 16; ks++) {
        uint32_t af[3][4], bf[3][2];
#pragma unroll
        for (int i = 0; i < 3; i++) {
            uint32_t addr = tb + (uint32_t)((Rm + i * 16 + (lane & 15)) * ROWB
                                            + ks * 32 + (lane >> 4) * 16);
            ldm_x4(af[i], addr);
        }
#pragma unroll
        for (int j = 0; j < 3; j++) {
            uint32_t addr = tb + (uint32_t)((Rn + j * 8 + (lane & 7)) * ROWB
                                            + ks * 32 + ((lane >> 3) & 1) * 16);
            ldm_x2(bf[j], addr);
        }
#pragma unroll
        for (int i = 0; i < 3; i++)
#pragma unroll
            for (int j = 0; j < 3; j++) mma_bf16(acc[i][j], af[i], bf[j]);
    }
}

__global__ void __launch_bounds__(256, 2)
k_fused(const float* __restrict__ x, const float* __restrict__ ea, int E) {
    extern __shared__ __align__(16) char dsm[];   // 2 * TILE_B
    int tid = threadIdx.x;
    int lane = tid & 31, w = tid >> 5;
    int warp_m = w >> 2, warp_n = w & 3;   // 2 x 4
    int Rm = warp_m * 48;                  // 3 x 16 rows
    int Rn = warp_n * 24;                  // 3 x 8 cols

    float acc[3][3][4];
#pragma unroll
    for (int i = 0; i < 3; i++)
#pragma unroll
        for (int j = 0; j < 3; j++)
#pragma unroll
            for (int q = 0; q < 4; q++) acc[i][j][q] = 0.f;

    float s0 = 0.f, s1 = 0.f, s2 = 0.f;
    float aS0 = 0.f, aS1 = 0.f, aS2 = 0.f;
    int curRow = -1;

    int nchunk = (E + KB - 1) / KB;
    int wbuf = 0, have = 0;
    for (int c = blockIdx.x; c < nchunk; c += gridDim.x) {
        long long base = (long long)c * KB;
        char* tp = dsm + wbuf * TILE_B;
        float v0[8], v1[8], v2[8];
        int rw[8];

        // ---- half 0: issue gather LDGs (scoreboard pending) ----------------
        fused_load8(x, ea, E, base + w * 16, lane, v0, v1, v2, rw);

        // ---- overlap: MMA phase of previous chunk (other buffer) -----------
        if (have) mma_phase(dsm + (wbuf ^ 1) * TILE_B, Rm, Rn, lane, acc);

        // ---- consume half 0: pack/store + seg-reduce ------------------------
        {
            int ee0 = w * 16;
#pragma unroll
            for (int u = 0; u < 8; u += 2) {
                s0 += v0[u] + v0[u + 1];
                s1 += v1[u] + v1[u + 1];
                s2 += v2[u] + v2[u + 1];
                __nv_bfloat162 b0 = __floats2bfloat162_rn(v0[u], v0[u + 1]);
                __nv_bfloat162 b1 = __floats2bfloat162_rn(v1[u], v1[u + 1]);
                __nv_bfloat162 b2 = __floats2bfloat162_rn(v2[u], v2[u + 1]);
                int eo = (ee0 + u) * 2;
                *(__nv_bfloat162*)(tp + lane * ROWB + eo) = b0;
                *(__nv_bfloat162*)(tp + (32 + lane) * ROWB + eo) = b1;
                *(__nv_bfloat162*)(tp + (64 + lane) * ROWB + eo) = b2;
            }
#pragma unroll
            for (int u = 0; u < 8; u++) {
                if (rw[u] != curRow) {
                    if (curRow >= 0) {
                        float* dst = g_S + (size_t)curRow * CH;
                        atomicAdd(&dst[lane], aS0);
                        atomicAdd(&dst[32 + lane], aS1);
                        if (lane < 24) atomicAdd(&dst[64 + lane], aS2);
                    }
                    curRow = rw[u];
                    aS0 = 0.f; aS1 = 0.f; aS2 = 0.f;
                }
                aS0 += v0[u]; aS1 += v1[u]; aS2 += v2[u];
            }
        }

        // ---- half 1 ----------------------------------------------------------
        fused_load8(x, ea, E, base + w * 16 + 8, lane, v0, v1, v2, rw);
        {
            int ee0 = w * 16 + 8;
#pragma unroll
            for (int u = 0; u < 8; u += 2) {
                s0 += v0[u] + v0[u + 1];
                s1 += v1[u] + v1[u + 1];
                s2 += v2[u] + v2[u + 1];
                __nv_bfloat162 b0 = __floats2bfloat162_rn(v0[u], v0[u + 1]);
                __nv_bfloat162 b1 = __floats2bfloat162_rn(v1[u], v1[u + 1]);
                __nv_bfloat162 b2 = __floats2bfloat162_rn(v2[u], v2[u + 1]);
                int eo = (ee0 + u) * 2;
                *(__nv_bfloat162*)(tp + lane * ROWB + eo) = b0;
                *(__nv_bfloat162*)(tp + (32 + lane) * ROWB + eo) = b1;
                *(__nv_bfloat162*)(tp + (64 + lane) * ROWB + eo) = b2;
            }
#pragma unroll
            for (int u = 0; u < 8; u++) {
                if (rw[u] != curRow) {
                    if (curRow >= 0) {
                        float* dst = g_S + (size_t)curRow * CH;
                        atomicAdd(&dst[lane], aS0);
                        atomicAdd(&dst[32 + lane], aS1);
                        if (lane < 24) atomicAdd(&dst[64 + lane], aS2);
                    }
                    curRow = rw[u];
                    aS0 = 0.f; aS1 = 0.f; aS2 = 0.f;
                }
                aS0 += v0[u]; aS1 += v1[u]; aS2 += v2[u];
            }
        }
        __syncthreads();   // stores of wbuf visible; prior mma on wbuf^1 complete
        have = 1;
        wbuf ^= 1;
    }
    // epilogue: MMA for the last stored chunk
    if (have) mma_phase(dsm + (wbuf ^ 1) * TILE_B, Rm, Rn, lane, acc);

    if (curRow >= 0) {
        float* dst = g_S + (size_t)curRow * CH;
        atomicAdd(&dst[lane], aS0);
        atomicAdd(&dst[32 + lane], aS1);
        if (lane < 24) atomicAdd(&dst[64 + lane], aS2);
    }
#pragma unroll
    for (int i = 0; i < 3; i++)
#pragma unroll
        for (int j = 0; j < 3; j++) {
            int row = Rm + i * 16 + (lane >> 2);
            int col = Rn + j * 8 + (lane & 3) * 2;
            atomicAdd(&g_M[row * CH + col], acc[i][j][0]);
            atomicAdd(&g_M[row * CH + col + 1], acc[i][j][1]);
            atomicAdd(&g_M[(row + 8) * CH + col], acc[i][j][2]);
            atomicAdd(&g_M[(row + 8) * CH + col + 1], acc[i][j][3]);
        }
    atomicAdd(&g_sv[lane], s0);
    atomicAdd(&g_sv[32 + lane], s1);
    if (lane < 24) atomicAdd(&g_sv[64 + lane], s2);
}

// ---------------- BN stats --------------------------------------------------
__global__ void k_bn(const float* __restrict__ W1, const float* __restrict__ b1,
                     const float* __restrict__ gamma, float fE) {
    int c = blockIdx.x;
    int t = threadIdx.x;  // 96 threads
    __shared__ float w[CH];
    __shared__ float rq[CH];
    __shared__ float rs[CH];
    w[t] = (t < 88) ? W1[t * OC + c] : 0.f;
    __syncthreads();
    float q = 0.f;
    if (t < 88) {
        const float* Mr = g_M + t * CH;
        for (int k = 0; k < 88; k++) q += Mr[k] * w[k];
        q *= w[t];
    }
    rq[t] = q;
    rs[t] = (t < 88) ? g_sv[t] * w[t] : 0.f;
    __syncthreads();
    if (t == 0) {
        float Q = 0.f, SW = 0.f;
        for (int i = 0; i < 88; i++) { Q += rq[i]; SW += rs[i]; }
        float b = b1[c];
        float mean = SW / fE + b;
        float ex2 = (Q + 2.f * b * SW) / fE + b * b;
        float var = ex2 - mean * mean;
        g_mean[c] = mean;
        g_scale[c] = gamma[c] * rsqrtf(var + EPSV);
    }
}

// ---------------- node output: f32x2 packed math, 4 nodes per warp ----------
__global__ void k_out(const float* __restrict__ x, const float* __restrict__ W1,
                      const float* __restrict__ b1, const float* __restrict__ beta,
                      const float* __restrict__ W2, const float* __restrict__ b2,
                      float* __restrict__ out, int N) {
    extern __shared__ float2 smp[];
    float2* W1pA = smp;                // 2816
    float2* W1pB = smp + 88 * 32;      // 2816
    float2* W2p  = smp + 2 * 88 * 32;  // 4224
    int tid = threadIdx.x;
    for (int i = tid; i < 88 * 32; i += blockDim.x) {
        int cc = i >> 5, l = i & 31;
        W1pA[i] = make_float2(W1[cc * OC + l], W1[cc * OC + 32 + l]);
        W1pB[i] = make_float2(W1[cc * OC + 64 + l], W1[cc * OC + 96 + l]);
    }
    for (int i = tid; i < 132 * 32; i += blockDim.x) {
        int cc = i >> 5, l = i & 31;
        W2p[i] = make_float2(W2[cc * OUTC + l], W2[cc * OUTC + 32 + l]);
    }
    __syncthreads();
    int lane = tid & 31;
    int warp = (blockIdx.x * blockDim.x + tid) >> 5;
    int nw = (gridDim.x * blockDim.x) >> 5;
    float mn0 = g_mean[lane], mn1 = g_mean[32 + lane], mn2 = g_mean[64 + lane], mn3 = g_mean[96 + lane];
    float sc0 = g_scale[lane], sc1 = g_scale[32 + lane], sc2 = g_scale[64 + lane], sc3 = g_scale[96 + lane];
    float bt0 = beta[lane], bt1 = beta[32 + lane], bt2 = beta[64 + lane], bt3 = beta[96 + lane];
    float bo0 = b1[lane], bo1 = b1[32 + lane], bo2 = b1[64 + lane], bo3 = b1[96 + lane];
    float bb0 = b2[lane], bb1 = b2[32 + lane];
    unsigned long long bbP = pack2(bb0, bb1);

    for (int n0 = warp * 4; n0 < N; n0 += nw * 4) {
        float sr0[4], sr1[4], sr2[4], rcp[4], tv[4];
#pragma unroll
        for (int m = 0; m < 4; m++) {
            int n = n0 + m;
            if (n < N) {
                const float* so = g_S + (size_t)n * CH;
                sr0[m] = so[lane]; sr1[m] = so[32 + lane]; sr2[m] = so[64 + lane];
                int cnt = g_off[n + 1] - g_off[n];
                tv[m] = (cnt > 0) ? 1.f : 0.f;
                rcp[m] = (cnt > 0) ? 1.f / (float)cnt : 0.f;
            } else { sr0[m] = sr1[m] = sr2[m] = 0.f; tv[m] = 0.f; rcp[m] = 0.f; }
        }
        unsigned long long aA[4], aB[4];
#pragma unroll
        for (int m = 0; m < 4; m++) { aA[m] = 0ull; aB[m] = 0ull; }
#pragma unroll
        for (int cc = 0; cc < 32; cc++) {
            unsigned long long wA = *(const unsigned long long*)&W1pA[cc * 32 + lane];
            unsigned long long wB = *(const unsigned long long*)&W1pB[cc * 32 + lane];
#pragma unroll
            for (int m = 0; m < 4; m++) {
                unsigned long long vv = packdup(__shfl_sync(0xffffffffu, sr0[m], cc));
                fma2(aA[m], vv, wA); fma2(aB[m], vv, wB);
            }
        }
#pragma unroll
        for (int cc = 0; cc < 32; cc++) {
            unsigned long long wA = *(const unsigned long long*)&W1pA[(32 + cc) * 32 + lane];
            unsigned long long wB = *(const unsigned long long*)&W1pB[(32 + cc) * 32 + lane];
#pragma unroll
            for (int m = 0; m < 4; m++) {
                unsigned long long vv = packdup(__shfl_sync(0xffffffffu, sr1[m], cc));
                fma2(aA[m], vv, wA); fma2(aB[m], vv, wB);
            }
        }
#pragma unroll
        for (int cc = 0; cc < 24; cc++) {
            unsigned long long wA = *(const unsigned long long*)&W1pA[(64 + cc) * 32 + lane];
            unsigned long long wB = *(const unsigned long long*)&W1pB[(64 + cc) * 32 + lane];
#pragma unroll
            for (int m = 0; m < 4; m++) {
                unsigned long long vv = packdup(__shfl_sync(0xffffffffu, sr2[m], cc));
                fma2(aA[m], vv, wA); fma2(aB[m], vv, wB);
            }
        }
        float ag0[4], ag1[4], ag2[4], ag3[4];
#pragma unroll
        for (int m = 0; m < 4; m++) {
            float2 vA = *(float2*)&aA[m];
            float2 vB = *(float2*)&aB[m];
            ag0[m] = ((vA.x * rcp[m] + bo0 - mn0) * sc0 + bt0) * tv[m];
            ag1[m] = ((vA.y * rcp[m] + bo1 - mn1) * sc1 + bt1) * tv[m];
            ag2[m] = ((vB.x * rcp[m] + bo2 - mn2) * sc2 + bt2) * tv[m];
            ag3[m] = ((vB.y * rcp[m] + bo3 - mn3) * sc3 + bt3) * tv[m];
        }
        unsigned long long oP[4];
#pragma unroll
        for (int m = 0; m < 4; m++) oP[m] = bbP;
#pragma unroll
        for (int k = 0; k < 4; k++) {
            unsigned long long wp = *(const unsigned long long*)&W2p[k * 32 + lane];
#pragma unroll
            for (int m = 0; m < 4; m++) {
                int n = n0 + m;
                float xv = (n < N) ? x[(size_t)n * 4 + k] : 0.f;
                fma2(oP[m], packdup(xv), wp);
            }
        }
#pragma unroll
        for (int cc = 0; cc < 32; cc++) {
            unsigned long long wp = *(const unsigned long long*)&W2p[(4 + cc) * 32 + lane];
#pragma unroll
            for (int m = 0; m < 4; m++)
                fma2(oP[m], packdup(__shfl_sync(0xffffffffu, ag0[m], cc)), wp);
        }
#pragma unroll
        for (int cc = 0; cc < 32; cc++) {
            unsigned long long wp = *(const unsigned long long*)&W2p[(36 + cc) * 32 + lane];
#pragma unroll
            for (int m = 0; m < 4; m++)
                fma2(oP[m], packdup(__shfl_sync(0xffffffffu, ag1[m], cc)), wp);
        }
#pragma unroll
        for (int cc = 0; cc < 32; cc++) {
            unsigned long long wp = *(const unsigned long long*)&W2p[(68 + cc) * 32 + lane];
#pragma unroll
            for (int m = 0; m < 4; m++)
                fma2(oP[m], packdup(__shfl_sync(0xffffffffu, ag2[m], cc)), wp);
        }
#pragma unroll
        for (int cc = 0; cc < 32; cc++) {
            unsigned long long wp = *(const unsigned long long*)&W2p[(100 + cc) * 32 + lane];
#pragma unroll
            for (int m = 0; m < 4; m++)
                fma2(oP[m], packdup(__shfl_sync(0xffffffffu, ag3[m], cc)), wp);
        }
#pragma unroll
        for (int m = 0; m < 4; m++) {
            int n = n0 + m;
            if (n < N) {
                float2 o = *(float2*)&oP[m];
                out[(size_t)n * 64 + lane] = fmaxf(o.x, 0.f);
                out[(size_t)n * 64 + 32 + lane] = fmaxf(o.y, 0.f);
            }
        }
    }
}

// ---------------- launcher --------------------------------------------------
extern "C" void kernel_launch(void* const* d_in, const int* in_sizes, int n_in,
                              void* d_out, int out_size) {
    const float* x     = (const float*)d_in[0];
    const void*  ei    = d_in[1];
    const float* ea    = (const float*)d_in[2];
    const float* W1    = (const float*)d_in[3];
    const float* b1    = (const float*)d_in[4];
    const float* gamma = (const float*)d_in[5];
    const float* beta  = (const float*)d_in[6];
    const float* W2    = (const float*)d_in[7];
    const float* b2    = (const float*)d_in[8];
    float* out = (float*)d_out;
    int N = in_sizes[0] / 4;
    int E = in_sizes[2] / 84;
    int nb = (N + SCAN_CH - 1) / SCAN_CH;

    k_detect<<<1, 32>>>(ei);
    k_zero<<<512, 256>>>(N);
    k_convhist<<<512, 256>>>(ei, E);
    k_scanA<<<nb, 1024>>>(N);
    k_scanC<<<(N + 255) / 256, 256>>>(N, nb, E);
    k_perm<<<512, 256>>>(E);

    const int msmem = 2 * TILE_B;   // 52224 B
    cudaFuncSetAttribute(k_fused, cudaFuncAttributeMaxDynamicSharedMemorySize, msmem);
    k_fused<<<296, 256, msmem>>>(x, ea, E);

    k_bn<<<128, 96>>>(W1, b1, gamma, (float)E);
    const int osmem = (2 * 88 * 32 + 132 * 32) * 8;  // 78848 B
    cudaFuncSetAttribute(k_out, cudaFuncAttributeMaxDynamicSharedMemorySize, osmem);
    k_out<<<296, 256, osmem>>>(x, W1, b1, beta, W2, b2, out, N);
}